// round 1
// baseline (speedup 1.0000x reference)
#include <cuda_runtime.h>
#include <cstdint>

// Problem constants
#define BATCH 32
#define VLEN  4096
#define HDIM  1024

// Scratch (allowed as __device__ globals)
__device__ float g_qb[BATCH * HDIM];      // Wq*query + bias, per (b, o)
__device__ float g_score[BATCH * VLEN];   // pre-softmax scores

// ---------------------------------------------------------------------------
// Packed f32x2 helpers (sm_100+/sm_103a): FFMA2 is only reachable via PTX.
// ---------------------------------------------------------------------------
__device__ __forceinline__ unsigned long long pack2(float lo, float hi) {
    unsigned long long r;
    asm("mov.b64 %0, {%1, %2};" : "=l"(r) : "f"(lo), "f"(hi));
    return r;
}
__device__ __forceinline__ void ffma2(unsigned long long& d,
                                      unsigned long long a,
                                      unsigned long long b) {
    asm("fma.rn.f32x2 %0, %1, %2, %0;" : "+l"(d) : "l"(a), "l"(b));
}
__device__ __forceinline__ float lo32(unsigned long long u) {
    return __uint_as_float((unsigned int)(u & 0xffffffffull));
}
__device__ __forceinline__ float hi32(unsigned long long u) {
    return __uint_as_float((unsigned int)(u >> 32));
}

// ---------------------------------------------------------------------------
// Kernel 1: qb[b][o] = bias[o] + sum_h Wq[o][h] * query[b][h]
// One warp per (b, o).
// ---------------------------------------------------------------------------
__global__ void qb_kernel(const float* __restrict__ query,
                          const float* __restrict__ Wq,
                          const float* __restrict__ bias) {
    int w    = (blockIdx.x * blockDim.x + threadIdx.x) >> 5;
    int lane = threadIdx.x & 31;
    int b = w / HDIM;
    int o = w % HDIM;
    const float* wrow = Wq + (size_t)o * HDIM;
    const float* qrow = query + (size_t)b * HDIM;
    float s = 0.0f;
#pragma unroll 8
    for (int h = lane; h < HDIM; h += 32) s += wrow[h] * qrow[h];
#pragma unroll
    for (int off = 16; off; off >>= 1) s += __shfl_xor_sync(0xffffffffu, s, off);
    if (lane == 0) g_qb[w] = s + bias[o];
}

// ---------------------------------------------------------------------------
// Kernel 2: fused score GEMM.
// score[b][v] = bs + sum_o Ws[o] * tanh( sum_h Wk[o][h]*key[b][v][h] + qb[b][o] )
//
// Block: BM=64 rows (v), iterates nt=0..3 over BN=256 col (o) tiles, BK=16.
// 256 threads = 8 (ty, row groups) x 32 (tx, col groups), 8x8 micro-tile,
// accumulated in f32x2 pairs (FFMA2).
// ---------------------------------------------------------------------------
#define BM 64
#define BN 256
#define BK 16
#define AP 68    // a_s row pitch (floats): keeps 16B alignment for float4 reads
#define BP 260   // b_s row pitch (floats): 16B-aligned per-k rows

__global__ void __launch_bounds__(256, 2)
score_kernel(const float* __restrict__ key,
             const float* __restrict__ Wk,
             const float* __restrict__ Ws,
             const float* __restrict__ bs) {
    __shared__ __align__(16) float a_s[BK * AP];  // a_s[k][m] = key tile
    __shared__ __align__(16) float b_s[BK * BP];  // b_s[k][n] = Wk tile (transposed)

    const int tid = threadIdx.x;
    const int tx  = tid & 31;   // col group
    const int ty  = tid >> 5;   // row group (== warp id)
    const int b   = blockIdx.y;
    const int v0  = blockIdx.x * BM;

    const float bs0 = bs[0];

    // per-thread row partial sums across all o
    float part[8];
#pragma unroll
    for (int i = 0; i < 8; i++) part[i] = 0.0f;

    // tile-load index precompute
    const int lm  = tid >> 2;          // 0..63 : row within tile for a-load
    const int lk4 = (tid & 3) * 4;     // k offset (float4) for both loads

    const size_t key_row0 = ((size_t)b * VLEN + v0) * HDIM;

    for (int nt = 0; nt < 4; nt++) {
        const int o0 = nt * BN;

        unsigned long long acc2[8][4];
#pragma unroll
        for (int i = 0; i < 8; i++)
#pragma unroll
            for (int p = 0; p < 4; p++) acc2[i][p] = 0ull;

        for (int kt = 0; kt < HDIM / BK; kt++) {
            const int h0 = kt * BK;
            __syncthreads();
            // ---- load key tile: a_s[k][m] = key[b][v0+m][h0+k] ----
            {
                const float4 g = *reinterpret_cast<const float4*>(
                    key + key_row0 + (size_t)lm * HDIM + h0 + lk4);
                a_s[(lk4 + 0) * AP + lm] = g.x;
                a_s[(lk4 + 1) * AP + lm] = g.y;
                a_s[(lk4 + 2) * AP + lm] = g.z;
                a_s[(lk4 + 3) * AP + lm] = g.w;
            }
            // ---- load Wk tile: b_s[k][n] = Wk[o0+n][h0+k] ----
#pragma unroll
            for (int p = 0; p < 4; p++) {
                const int n = (tid >> 2) + p * 64;
                const float4 g = *reinterpret_cast<const float4*>(
                    Wk + (size_t)(o0 + n) * HDIM + h0 + lk4);
                b_s[(lk4 + 0) * BP + n] = g.x;
                b_s[(lk4 + 1) * BP + n] = g.y;
                b_s[(lk4 + 2) * BP + n] = g.z;
                b_s[(lk4 + 3) * BP + n] = g.w;
            }
            __syncthreads();

            // ---- compute ----
#pragma unroll
            for (int k = 0; k < BK; k++) {
                const float4 av0 = *reinterpret_cast<const float4*>(&a_s[k * AP + ty * 8]);
                const float4 av1 = *reinterpret_cast<const float4*>(&a_s[k * AP + ty * 8 + 4]);
                const ulonglong2 bv0 = *reinterpret_cast<const ulonglong2*>(&b_s[k * BP + tx * 4]);
                const ulonglong2 bv1 = *reinterpret_cast<const ulonglong2*>(&b_s[k * BP + 128 + tx * 4]);
                unsigned long long bb[4] = {bv0.x, bv0.y, bv1.x, bv1.y};
                float ar[8] = {av0.x, av0.y, av0.z, av0.w, av1.x, av1.y, av1.z, av1.w};
#pragma unroll
                for (int i = 0; i < 8; i++) {
                    const unsigned long long aa = pack2(ar[i], ar[i]);
#pragma unroll
                    for (int p = 0; p < 4; p++) ffma2(acc2[i][p], aa, bb[p]);
                }
            }
        }

        // ---- epilogue for this col tile: tanh + Ws-weighted row reduction ----
#pragma unroll
        for (int p = 0; p < 4; p++) {
            const int colbase = o0 + ((p >= 2) ? 128 : 0) + tx * 4 + (p & 1) * 2;
#pragma unroll
            for (int half = 0; half < 2; half++) {
                const int col = colbase + half;
                const float ws = Ws[col];
                const float qb = g_qb[b * HDIM + col];
#pragma unroll
                for (int i = 0; i < 8; i++) {
                    const float v = (half == 0 ? lo32(acc2[i][p]) : hi32(acc2[i][p])) + qb;
                    part[i] += ws * tanhf(v);
                }
            }
        }
    }

    // ---- warp reduce partials (each warp owns rows ty*8 .. ty*8+7) ----
#pragma unroll
    for (int i = 0; i < 8; i++) {
        float s = part[i];
#pragma unroll
        for (int off = 16; off; off >>= 1) s += __shfl_xor_sync(0xffffffffu, s, off);
        if (tx == 0) g_score[b * VLEN + v0 + ty * 8 + i] = s + bs0;
    }
}

// ---------------------------------------------------------------------------
// Kernel 3: softmax over V=4096 per batch. One block per b, 256 threads.
// Writes attn into d_out attn region.
// ---------------------------------------------------------------------------
__global__ void softmax_kernel(float* __restrict__ attn_out) {
    __shared__ float red[256];
    const int b = blockIdx.x;
    const int t = threadIdx.x;
    const float* s = g_score + b * VLEN;

    float local[16];
    float mx = -1e30f;
#pragma unroll
    for (int i = 0; i < 16; i++) {
        local[i] = s[t + i * 256];
        mx = fmaxf(mx, local[i]);
    }
    red[t] = mx;
    __syncthreads();
    for (int o = 128; o; o >>= 1) {
        if (t < o) red[t] = fmaxf(red[t], red[t + o]);
        __syncthreads();
    }
    mx = red[0];
    __syncthreads();

    float sum = 0.0f;
#pragma unroll
    for (int i = 0; i < 16; i++) {
        local[i] = expf(local[i] - mx);
        sum += local[i];
    }
    red[t] = sum;
    __syncthreads();
    for (int o = 128; o; o >>= 1) {
        if (t < o) red[t] += red[t + o];
        __syncthreads();
    }
    const float inv = 1.0f / red[0];
#pragma unroll
    for (int i = 0; i < 16; i++) attn_out[b * VLEN + t + i * 256] = local[i] * inv;
}

// ---------------------------------------------------------------------------
// Kernel 4: context[b][h] = sum_v attn[b][v] * value[b][v][h]
// Grid (8 h-chunks, 32 b), 128 threads each owning one h. HBM-bound.
// ---------------------------------------------------------------------------
__global__ void context_kernel(const float* __restrict__ value,
                               const float* __restrict__ attn,
                               float* __restrict__ ctx) {
    __shared__ float a_s[VLEN];  // 16 KB
    const int b = blockIdx.y;
    const int h = blockIdx.x * 128 + threadIdx.x;
    const float* ap = attn + b * VLEN;
    for (int v = threadIdx.x; v < VLEN; v += 128) a_s[v] = ap[v];
    __syncthreads();

    const float* vp = value + ((size_t)b * VLEN) * HDIM + h;
    float acc0 = 0.f, acc1 = 0.f, acc2 = 0.f, acc3 = 0.f;
#pragma unroll 2
    for (int v = 0; v < VLEN; v += 4) {
        acc0 += a_s[v + 0] * vp[(size_t)(v + 0) * HDIM];
        acc1 += a_s[v + 1] * vp[(size_t)(v + 1) * HDIM];
        acc2 += a_s[v + 2] * vp[(size_t)(v + 2) * HDIM];
        acc3 += a_s[v + 3] * vp[(size_t)(v + 3) * HDIM];
    }
    ctx[b * HDIM + h] = (acc0 + acc1) + (acc2 + acc3);
}

// ---------------------------------------------------------------------------
// Launch. Input order (metadata): query, key, value, Wq, Wk, bias, Ws, bs.
// Output: context (32*1024 floats) then attn (32*4096 floats).
// ---------------------------------------------------------------------------
extern "C" void kernel_launch(void* const* d_in, const int* in_sizes, int n_in,
                              void* d_out, int out_size) {
    const float* query = (const float*)d_in[0];
    const float* key   = (const float*)d_in[1];
    const float* value = (const float*)d_in[2];
    const float* Wq    = (const float*)d_in[3];
    const float* Wk    = (const float*)d_in[4];
    const float* bias  = (const float*)d_in[5];
    const float* Ws    = (const float*)d_in[6];
    const float* bs    = (const float*)d_in[7];

    float* out  = (float*)d_out;
    float* ctx  = out;                    // (B, 1, H)
    float* attn = out + BATCH * HDIM;     // (B, V)

    qb_kernel<<<(BATCH * HDIM * 32) / 256, 256>>>(query, Wq, bias);
    score_kernel<<<dim3(VLEN / BM, BATCH), 256>>>(key, Wk, Ws, bs);
    softmax_kernel<<<BATCH, 256>>>(attn);
    context_kernel<<<dim3(HDIM / 128, BATCH), 128>>>(value, attn, ctx);
}

// round 3
// speedup vs baseline: 1.6280x; 1.6280x over previous
#include <cuda_runtime.h>
#include <cuda_bf16.h>
#include <cstdint>

#define BATCH 32
#define VLEN  4096
#define HDIM  1024

// ---------------- device scratch ----------------
__device__ float g_qb[BATCH * HDIM];
__device__ float g_score[BATCH * VLEN];
__device__ __align__(16) __nv_bfloat16 g_wk_hi[HDIM * HDIM];
__device__ __align__(16) __nv_bfloat16 g_wk_lo[HDIM * HDIM];

// ---------------- helpers ----------------
__device__ __forceinline__ uint32_t smem_u32(const void* p) {
    uint32_t a;
    asm("{ .reg .u64 t; cvta.to.shared.u64 t, %1; cvt.u32.u64 %0, t; }" : "=r"(a) : "l"(p));
    return a;
}
__device__ __forceinline__ void cp16(uint32_t saddr, const void* g) {
    asm volatile("cp.async.cg.shared.global [%0], [%1], 16;" :: "r"(saddr), "l"(g) : "memory");
}
#define CP_COMMIT() asm volatile("cp.async.commit_group;" ::: "memory")
#define CP_WAIT0()  asm volatile("cp.async.wait_group 0;" ::: "memory")

__device__ __forceinline__ void ldsm4(uint32_t* r, uint32_t addr) {
    asm volatile("ldmatrix.sync.aligned.m8n8.x4.shared.b16 {%0,%1,%2,%3}, [%4];"
                 : "=r"(r[0]), "=r"(r[1]), "=r"(r[2]), "=r"(r[3]) : "r"(addr));
}
__device__ __forceinline__ void mma_bf16(float* d, const uint32_t* a, uint32_t b0, uint32_t b1) {
    asm volatile("mma.sync.aligned.m16n8k16.row.col.f32.bf16.bf16.f32 "
                 "{%0,%1,%2,%3}, {%4,%5,%6,%7}, {%8,%9}, {%0,%1,%2,%3};"
                 : "+f"(d[0]), "+f"(d[1]), "+f"(d[2]), "+f"(d[3])
                 : "r"(a[0]), "r"(a[1]), "r"(a[2]), "r"(a[3]), "r"(b0), "r"(b1));
}
__device__ __forceinline__ uint32_t pkbf(__nv_bfloat16 a, __nv_bfloat16 b) {
    return (uint32_t)__bfloat16_as_ushort(a) | ((uint32_t)__bfloat16_as_ushort(b) << 16);
}
__device__ __forceinline__ void split2(float f, __nv_bfloat16& h, __nv_bfloat16& l) {
    h = __float2bfloat16(f);
    l = __float2bfloat16(f - __bfloat162float(h));
}
// fast accurate tanh: 1 - 2/(exp(2x)+1); __expf is MUFU-based, rel err ~1e-6
__device__ __forceinline__ float ftanh(float x) {
    float e = __expf(2.0f * x);
    return 1.0f - __fdividef(2.0f, e + 1.0f);
}

// ---------------- SMEM layout (bytes) ----------------
// per buffer: [Ahi 10240][Alo 10240][Bhi 20480][Blo 20480] = 61440; 2 buffers
#define OFF_ALO  10240
#define OFF_BHI  20480
#define OFF_BLO  40960
#define BUFSZ    61440
#define SM_QB    (2 * BUFSZ)          // 122880, 1024 floats
#define SM_WS    (SM_QB + 4096)       // 126976
#define SM_RED   (SM_WS + 4096)       // 131072, 512 floats
#define SM_TOTAL (SM_RED + 2048)      // 133120

// ---------------------------------------------------------------------------
// Kernel 1: qb[b][o] = bias[o] + sum_h Wq[o][h] * query[b][h]
// ---------------------------------------------------------------------------
__global__ void qb_kernel(const float* __restrict__ query,
                          const float* __restrict__ Wq,
                          const float* __restrict__ bias) {
    int w    = (blockIdx.x * blockDim.x + threadIdx.x) >> 5;
    int lane = threadIdx.x & 31;
    int b = w / HDIM;
    int o = w % HDIM;
    const float* wrow = Wq + (size_t)o * HDIM;
    const float* qrow = query + (size_t)b * HDIM;
    float s = 0.0f;
#pragma unroll 8
    for (int h = lane; h < HDIM; h += 32) s += wrow[h] * qrow[h];
#pragma unroll
    for (int off = 16; off; off >>= 1) s += __shfl_xor_sync(0xffffffffu, s, off);
    if (lane == 0) g_qb[w] = s + bias[o];
}

// ---------------------------------------------------------------------------
// Kernel 1b: split Wk into bf16 hi/lo device globals
// ---------------------------------------------------------------------------
__global__ void wk_split_kernel(const float* __restrict__ Wk) {
    int i = (blockIdx.x * 256 + threadIdx.x) * 4;
    float4 w = *reinterpret_cast<const float4*>(Wk + i);
    __nv_bfloat16 h0, h1, h2, h3, l0, l1, l2, l3;
    split2(w.x, h0, l0); split2(w.y, h1, l1);
    split2(w.z, h2, l2); split2(w.w, h3, l3);
    *reinterpret_cast<uint2*>(g_wk_hi + i) = make_uint2(pkbf(h0, h1), pkbf(h2, h3));
    *reinterpret_cast<uint2*>(g_wk_lo + i) = make_uint2(pkbf(l0, l1), pkbf(l2, l3));
}

// ---------------------------------------------------------------------------
// Kernel 2: score GEMM via mma.sync bf16 split (3 MMAs), fused tanh-reduce.
// Block: 128 v-rows x 256 o-cols per pass, 4 passes over o. K-chunk 32,
// double-buffered smem (pitch 40 bf16 = conflict-free LDSM), cp.async for Wk.
// ---------------------------------------------------------------------------
__global__ void __launch_bounds__(256, 1)
score_kernel(const float* __restrict__ key, const float* __restrict__ Ws) {
    extern __shared__ __align__(16) char smem[];
    const uint32_t sb = smem_u32(smem);
    const int tid  = threadIdx.x;
    const int lane = tid & 31;
    const int wid  = tid >> 5;
    const int wy   = wid >> 2;   // 0..1 : M group (64 rows)
    const int wx   = wid & 3;    // 0..3 : N group (64 cols)
    const int b    = blockIdx.y;
    const int v0   = blockIdx.x * 128;

    // stage qb + Ws for all 1024 o
    float* qbs = reinterpret_cast<float*>(smem + SM_QB);
    float* wss = reinterpret_cast<float*>(smem + SM_WS);
#pragma unroll
    for (int i = 0; i < 4; i++) {
        qbs[tid + i * 256] = g_qb[b * HDIM + tid + i * 256];
        wss[tid + i * 256] = Ws[tid + i * 256];
    }

    const float* keyb = key + ((size_t)b * VLEN + v0) * HDIM;

    // global-load thread mapping
    const int km = tid >> 1;            // key row 0..127
    const int kc = (tid & 1) * 16;      // key col base (fp32)
    const int wn = tid;                 // Wk row 0..255

    // ldsm per-lane base offset within a tile (pitch 80 B)
    const uint32_t aoff  = (uint32_t)((lane & 15) * 80 + (lane >> 4) * 16);
    const uint32_t Abase = sb + (uint32_t)(wy * 64 * 80) + aoff;
    const uint32_t Bbase = sb + OFF_BHI + (uint32_t)(wx * 64 * 80) + aoff;

    float d[4][8][4];
#pragma unroll
    for (int mt = 0; mt < 4; mt++)
#pragma unroll
        for (int j = 0; j < 8; j++)
#pragma unroll
            for (int q = 0; q < 4; q++) d[mt][j][q] = 0.0f;
    float part[8];
#pragma unroll
    for (int i = 0; i < 8; i++) part[i] = 0.0f;

    float4 kreg[4];

    // ---- prologue: chunk 0 into buffer 0 ----
    {
#pragma unroll
        for (int c = 0; c < 4; c++) {
            cp16(sb + OFF_BHI + wn * 80 + c * 16, g_wk_hi + (size_t)wn * HDIM + c * 8);
            cp16(sb + OFF_BLO + wn * 80 + c * 16, g_wk_lo + (size_t)wn * HDIM + c * 8);
        }
        CP_COMMIT();
#pragma unroll
        for (int i = 0; i < 4; i++)
            kreg[i] = *reinterpret_cast<const float4*>(keyb + (size_t)km * HDIM + kc + i * 4);
        char* bufp = smem;
#pragma unroll
        for (int i = 0; i < 4; i++) {
            __nv_bfloat16 h0, h1, h2, h3, l0, l1, l2, l3;
            split2(kreg[i].x, h0, l0); split2(kreg[i].y, h1, l1);
            split2(kreg[i].z, h2, l2); split2(kreg[i].w, h3, l3);
            const int boff = km * 80 + (kc + i * 4) * 2;
            *reinterpret_cast<uint2*>(bufp + boff)           = make_uint2(pkbf(h0, h1), pkbf(h2, h3));
            *reinterpret_cast<uint2*>(bufp + OFF_ALO + boff) = make_uint2(pkbf(l0, l1), pkbf(l2, l3));
        }
        CP_WAIT0();
        __syncthreads();
    }

    int cur = 0;
    for (int gc = 0; gc < 128; gc++) {
        const int nxt = cur ^ 1;
        // ---- issue loads for next chunk ----
        if (gc < 127) {
            const int n   = gc + 1;
            const int h0  = (n & 31) * 32;
            const int o0n = (n >> 5) * 256;
            const uint32_t bb = sb + (uint32_t)nxt * BUFSZ;
#pragma unroll
            for (int c = 0; c < 4; c++) {
                const size_t gi = (size_t)(o0n + wn) * HDIM + h0 + c * 8;
                cp16(bb + OFF_BHI + wn * 80 + c * 16, g_wk_hi + gi);
                cp16(bb + OFF_BLO + wn * 80 + c * 16, g_wk_lo + gi);
            }
            CP_COMMIT();
#pragma unroll
            for (int i = 0; i < 4; i++)
                kreg[i] = *reinterpret_cast<const float4*>(keyb + (size_t)km * HDIM + h0 + kc + i * 4);
        }

        // ---- compute current chunk ----
        {
            const uint32_t abuf = Abase + (uint32_t)cur * BUFSZ;
            const uint32_t bbuf = Bbase + (uint32_t)cur * BUFSZ;
#pragma unroll
            for (int ks = 0; ks < 2; ks++) {
                uint32_t Bh[4][4], Bl[4][4];
#pragma unroll
                for (int jj = 0; jj < 4; jj++) {
                    ldsm4(Bh[jj], bbuf + jj * 1280 + ks * 32);
                    ldsm4(Bl[jj], bbuf + 20480 + jj * 1280 + ks * 32);
                }
#pragma unroll
                for (int mt = 0; mt < 4; mt++) {
                    uint32_t Ah[4], Al[4];
                    ldsm4(Ah, abuf + mt * 1280 + ks * 32);
                    ldsm4(Al, abuf + OFF_ALO + mt * 1280 + ks * 32);
#pragma unroll
                    for (int jj = 0; jj < 4; jj++) {
#pragma unroll
                        for (int h = 0; h < 2; h++) {
                            float* dd = d[mt][jj * 2 + h];
                            mma_bf16(dd, Ah, Bh[jj][h], Bh[jj][2 + h]);
                            mma_bf16(dd, Al, Bh[jj][h], Bh[jj][2 + h]);
                            mma_bf16(dd, Ah, Bl[jj][h], Bl[jj][2 + h]);
                        }
                    }
                }
            }
        }

        // ---- store key for next chunk, wait Wk copies ----
        if (gc < 127) {
            char* bufp = smem + (size_t)nxt * BUFSZ;
#pragma unroll
            for (int i = 0; i < 4; i++) {
                __nv_bfloat16 h0, h1, h2, h3, l0, l1, l2, l3;
                split2(kreg[i].x, h0, l0); split2(kreg[i].y, h1, l1);
                split2(kreg[i].z, h2, l2); split2(kreg[i].w, h3, l3);
                const int boff = km * 80 + (kc + i * 4) * 2;
                *reinterpret_cast<uint2*>(bufp + boff)           = make_uint2(pkbf(h0, h1), pkbf(h2, h3));
                *reinterpret_cast<uint2*>(bufp + OFF_ALO + boff) = make_uint2(pkbf(l0, l1), pkbf(l2, l3));
            }
            CP_WAIT0();
        }
        __syncthreads();

        // ---- end of pass: tanh + Ws reduction, reset accumulators ----
        if ((gc & 31) == 31) {
            const int o0 = (gc >> 5) * 256;
            const int cb = o0 + wx * 64 + (lane & 3) * 2;
#pragma unroll
            for (int mt = 0; mt < 4; mt++) {
#pragma unroll
                for (int j = 0; j < 8; j++) {
                    const int o = cb + j * 8;
                    const float w0 = wss[o], w1 = wss[o + 1];
                    const float q0 = qbs[o], q1 = qbs[o + 1];
                    part[mt * 2 + 0] += w0 * ftanh(d[mt][j][0] + q0) + w1 * ftanh(d[mt][j][1] + q1);
                    part[mt * 2 + 1] += w0 * ftanh(d[mt][j][2] + q0) + w1 * ftanh(d[mt][j][3] + q1);
                    d[mt][j][0] = 0.0f; d[mt][j][1] = 0.0f;
                    d[mt][j][2] = 0.0f; d[mt][j][3] = 0.0f;
                }
            }
        }
        cur ^= 1;
    }

    // ---- cross-thread reduction ----
#pragma unroll
    for (int i = 0; i < 8; i++) {
        part[i] += __shfl_xor_sync(0xffffffffu, part[i], 1);
        part[i] += __shfl_xor_sync(0xffffffffu, part[i], 2);
    }
    float* red = reinterpret_cast<float*>(smem + SM_RED);
    if ((lane & 3) == 0) {
        const int r0 = wy * 64 + (lane >> 2);
#pragma unroll
        for (int mt = 0; mt < 4; mt++) {
            red[wx * 128 + r0 + mt * 16]     = part[mt * 2 + 0];
            red[wx * 128 + r0 + mt * 16 + 8] = part[mt * 2 + 1];
        }
    }
    __syncthreads();
    if (tid < 128) {
        const float s = red[tid] + red[128 + tid] + red[256 + tid] + red[384 + tid];
        g_score[b * VLEN + v0 + tid] = s;
    }
}

// ---------------------------------------------------------------------------
// Kernel 3: softmax over V=4096 per batch (bs dropped: shift-invariant)
// ---------------------------------------------------------------------------
__global__ void softmax_kernel(float* __restrict__ attn_out) {
    __shared__ float red[256];
    const int b = blockIdx.x;
    const int t = threadIdx.x;
    const float* s = g_score + b * VLEN;

    float local[16];
    float mx = -1e30f;
#pragma unroll
    for (int i = 0; i < 16; i++) {
        local[i] = s[t + i * 256];
        mx = fmaxf(mx, local[i]);
    }
    red[t] = mx;
    __syncthreads();
    for (int o = 128; o; o >>= 1) {
        if (t < o) red[t] = fmaxf(red[t], red[t + o]);
        __syncthreads();
    }
    mx = red[0];
    __syncthreads();

    float sum = 0.0f;
#pragma unroll
    for (int i = 0; i < 16; i++) {
        local[i] = expf(local[i] - mx);
        sum += local[i];
    }
    red[t] = sum;
    __syncthreads();
    for (int o = 128; o; o >>= 1) {
        if (t < o) red[t] += red[t + o];
        __syncthreads();
    }
    const float inv = 1.0f / red[0];
#pragma unroll
    for (int i = 0; i < 16; i++) attn_out[b * VLEN + t + i * 256] = local[i] * inv;
}

// ---------------------------------------------------------------------------
// Kernel 4: context[b][h] = sum_v attn[b][v] * value[b][v][h]
// ---------------------------------------------------------------------------
__global__ void context_kernel(const float* __restrict__ value,
                               const float* __restrict__ attn,
                               float* __restrict__ ctx) {
    __shared__ float a_s[VLEN];
    const int b = blockIdx.y;
    const int h = blockIdx.x * 128 + threadIdx.x;
    const float* ap = attn + b * VLEN;
    for (int v = threadIdx.x; v < VLEN; v += 128) a_s[v] = ap[v];
    __syncthreads();

    const float* vp = value + ((size_t)b * VLEN) * HDIM + h;
    float acc[4] = {0.f, 0.f, 0.f, 0.f};
    for (int v = 0; v < VLEN; v += 16) {
#pragma unroll
        for (int j = 0; j < 16; j++)
            acc[j & 3] += a_s[v + j] * vp[(size_t)(v + j) * HDIM];
    }
    ctx[b * HDIM + h] = (acc[0] + acc[1]) + (acc[2] + acc[3]);
}

// ---------------------------------------------------------------------------
// Launch. Inputs: query, key, value, Wq, Wk, bias, Ws, bs.
// Output: context (32*1024) then attn (32*4096).
// ---------------------------------------------------------------------------
extern "C" void kernel_launch(void* const* d_in, const int* in_sizes, int n_in,
                              void* d_out, int out_size) {
    const float* query = (const float*)d_in[0];
    const float* key   = (const float*)d_in[1];
    const float* value = (const float*)d_in[2];
    const float* Wq    = (const float*)d_in[3];
    const float* Wk    = (const float*)d_in[4];
    const float* bias  = (const float*)d_in[5];
    const float* Ws    = (const float*)d_in[6];

    float* out  = (float*)d_out;
    float* ctx  = out;                    // (B, 1, H)
    float* attn = out + BATCH * HDIM;     // (B, V)

    cudaFuncSetAttribute(score_kernel, cudaFuncAttributeMaxDynamicSharedMemorySize, SM_TOTAL);

    qb_kernel<<<(BATCH * HDIM * 32) / 256, 256>>>(query, Wq, bias);
    wk_split_kernel<<<(HDIM * HDIM) / (256 * 4), 256>>>(Wk);
    score_kernel<<<dim3(VLEN / 128, BATCH), 256, SM_TOTAL>>>(key, Ws);
    softmax_kernel<<<BATCH, 256>>>(attn);
    context_kernel<<<dim3(HDIM / 128, BATCH), 128>>>(value, attn, ctx);
}

// round 4
// speedup vs baseline: 2.5207x; 1.5483x over previous
#include <cuda_runtime.h>
#include <cuda_bf16.h>
#include <cstdint>

#define BATCH 32
#define VLEN  4096
#define HDIM  1024

// ---------------- device scratch ----------------
__device__ float g_qb[BATCH * HDIM];
__device__ float g_score[BATCH * VLEN];
__device__ __align__(16) __nv_bfloat16 g_wk_hi[HDIM * HDIM];
__device__ float g_ctx_part[8 * BATCH * HDIM];   // v-split context partials

// ---------------- helpers ----------------
__device__ __forceinline__ uint32_t smem_u32(const void* p) {
    uint32_t a;
    asm("{ .reg .u64 t; cvta.to.shared.u64 t, %1; cvt.u32.u64 %0, t; }" : "=r"(a) : "l"(p));
    return a;
}
__device__ __forceinline__ void cp16(uint32_t saddr, const void* g) {
    asm volatile("cp.async.cg.shared.global [%0], [%1], 16;" :: "r"(saddr), "l"(g) : "memory");
}
#define CP_COMMIT() asm volatile("cp.async.commit_group;" ::: "memory")
#define CP_WAIT0()  asm volatile("cp.async.wait_group 0;" ::: "memory")

__device__ __forceinline__ void ldsm4(uint32_t* r, uint32_t addr) {
    asm volatile("ldmatrix.sync.aligned.m8n8.x4.shared.b16 {%0,%1,%2,%3}, [%4];"
                 : "=r"(r[0]), "=r"(r[1]), "=r"(r[2]), "=r"(r[3]) : "r"(addr));
}
__device__ __forceinline__ void mma_bf16(float* d, const uint32_t* a, uint32_t b0, uint32_t b1) {
    asm volatile("mma.sync.aligned.m16n8k16.row.col.f32.bf16.bf16.f32 "
                 "{%0,%1,%2,%3}, {%4,%5,%6,%7}, {%8,%9}, {%0,%1,%2,%3};"
                 : "+f"(d[0]), "+f"(d[1]), "+f"(d[2]), "+f"(d[3])
                 : "r"(a[0]), "r"(a[1]), "r"(a[2]), "r"(a[3]), "r"(b0), "r"(b1));
}
__device__ __forceinline__ uint32_t pkbf(__nv_bfloat16 a, __nv_bfloat16 b) {
    return (uint32_t)__bfloat16_as_ushort(a) | ((uint32_t)__bfloat16_as_ushort(b) << 16);
}
__device__ __forceinline__ void split2(float f, __nv_bfloat16& h, __nv_bfloat16& l) {
    h = __float2bfloat16(f);
    l = __float2bfloat16(f - __bfloat162float(h));
}
// fast tanh: 1 - 2/(exp(2x)+1); MUFU-based, rel err ~1e-6
__device__ __forceinline__ float ftanh(float x) {
    float e = __expf(2.0f * x);
    return 1.0f - __fdividef(2.0f, e + 1.0f);
}

// ---------------- SMEM layout (bytes) ----------------
// per buffer: [Ahi 10240][Alo 10240][Bhi 20480] = 40960; 2 buffers
#define OFF_ALO  10240
#define OFF_BHI  20480
#define BUFSZ    40960
#define SM_QB    (2 * BUFSZ)          // 81920, 1024 floats
#define SM_WS    (SM_QB + 4096)
#define SM_RED   (SM_WS + 4096)
#define SM_TOTAL (SM_RED + 2048)      // 92160

// ---------------------------------------------------------------------------
// Kernel 1: qb[b][o] = bias[o] + sum_h Wq[o][h] * query[b][h]
// ---------------------------------------------------------------------------
__global__ void qb_kernel(const float* __restrict__ query,
                          const float* __restrict__ Wq,
                          const float* __restrict__ bias) {
    int w    = (blockIdx.x * blockDim.x + threadIdx.x) >> 5;
    int lane = threadIdx.x & 31;
    int b = w / HDIM;
    int o = w % HDIM;
    const float* wrow = Wq + (size_t)o * HDIM;
    const float* qrow = query + (size_t)b * HDIM;
    float s = 0.0f;
#pragma unroll 8
    for (int h = lane; h < HDIM; h += 32) s += wrow[h] * qrow[h];
#pragma unroll
    for (int off = 16; off; off >>= 1) s += __shfl_xor_sync(0xffffffffu, s, off);
    if (lane == 0) g_qb[w] = s + bias[o];
}

// ---------------------------------------------------------------------------
// Kernel 1b: round Wk to bf16 (single, round-to-nearest)
// ---------------------------------------------------------------------------
__global__ void wk_split_kernel(const float* __restrict__ Wk) {
    int i = (blockIdx.x * 256 + threadIdx.x) * 4;
    float4 w = *reinterpret_cast<const float4*>(Wk + i);
    *reinterpret_cast<uint2*>(g_wk_hi + i) =
        make_uint2(pkbf(__float2bfloat16(w.x), __float2bfloat16(w.y)),
                   pkbf(__float2bfloat16(w.z), __float2bfloat16(w.w)));
}

// ---------------------------------------------------------------------------
// Kernel 2: score GEMM, 2 bf16 MMAs per product (key split hi/lo, Wk bf16).
// Block: 128 v-rows x 256 o-cols per pass, 4 passes. K-chunk 32, double buffer.
// ---------------------------------------------------------------------------
__global__ void __launch_bounds__(256, 1)
score_kernel(const float* __restrict__ key, const float* __restrict__ Ws) {
    extern __shared__ __align__(16) char smem[];
    const uint32_t sb = smem_u32(smem);
    const int tid  = threadIdx.x;
    const int lane = tid & 31;
    const int wid  = tid >> 5;
    const int wy   = wid >> 2;   // 0..1 : M group (64 rows)
    const int wx   = wid & 3;    // 0..3 : N group (64 cols)
    const int b    = blockIdx.y;
    const int v0   = blockIdx.x * 128;

    float* qbs = reinterpret_cast<float*>(smem + SM_QB);
    float* wss = reinterpret_cast<float*>(smem + SM_WS);
#pragma unroll
    for (int i = 0; i < 4; i++) {
        qbs[tid + i * 256] = g_qb[b * HDIM + tid + i * 256];
        wss[tid + i * 256] = Ws[tid + i * 256];
    }

    const float* keyb = key + ((size_t)b * VLEN + v0) * HDIM;

    const int km = tid >> 1;            // key row 0..127
    const int kc = (tid & 1) * 16;      // key col base (fp32)
    const int wn = tid;                 // Wk row 0..255

    const uint32_t aoff  = (uint32_t)((lane & 15) * 80 + (lane >> 4) * 16);
    const uint32_t Abase = sb + (uint32_t)(wy * 64 * 80) + aoff;
    const uint32_t Bbase = sb + OFF_BHI + (uint32_t)(wx * 64 * 80) + aoff;

    float d[4][8][4];
#pragma unroll
    for (int mt = 0; mt < 4; mt++)
#pragma unroll
        for (int j = 0; j < 8; j++)
#pragma unroll
            for (int q = 0; q < 4; q++) d[mt][j][q] = 0.0f;
    float part[8];
#pragma unroll
    for (int i = 0; i < 8; i++) part[i] = 0.0f;

    float4 kreg[4];

    // ---- prologue: chunk 0 into buffer 0 ----
    {
#pragma unroll
        for (int c = 0; c < 4; c++)
            cp16(sb + OFF_BHI + wn * 80 + c * 16, g_wk_hi + (size_t)wn * HDIM + c * 8);
        CP_COMMIT();
#pragma unroll
        for (int i = 0; i < 4; i++)
            kreg[i] = *reinterpret_cast<const float4*>(keyb + (size_t)km * HDIM + kc + i * 4);
        char* bufp = smem;
#pragma unroll
        for (int i = 0; i < 4; i++) {
            __nv_bfloat16 h0, h1, h2, h3, l0, l1, l2, l3;
            split2(kreg[i].x, h0, l0); split2(kreg[i].y, h1, l1);
            split2(kreg[i].z, h2, l2); split2(kreg[i].w, h3, l3);
            const int boff = km * 80 + (kc + i * 4) * 2;
            *reinterpret_cast<uint2*>(bufp + boff)           = make_uint2(pkbf(h0, h1), pkbf(h2, h3));
            *reinterpret_cast<uint2*>(bufp + OFF_ALO + boff) = make_uint2(pkbf(l0, l1), pkbf(l2, l3));
        }
        CP_WAIT0();
        __syncthreads();
    }

    int cur = 0;
    for (int gc = 0; gc < 128; gc++) {
        const int nxt = cur ^ 1;
        // ---- issue loads for next chunk ----
        if (gc < 127) {
            const int n   = gc + 1;
            const int h0  = (n & 31) * 32;
            const int o0n = (n >> 5) * 256;
            const uint32_t bb = sb + (uint32_t)nxt * BUFSZ;
#pragma unroll
            for (int c = 0; c < 4; c++)
                cp16(bb + OFF_BHI + wn * 80 + c * 16,
                     g_wk_hi + (size_t)(o0n + wn) * HDIM + h0 + c * 8);
            CP_COMMIT();
#pragma unroll
            for (int i = 0; i < 4; i++)
                kreg[i] = *reinterpret_cast<const float4*>(keyb + (size_t)km * HDIM + h0 + kc + i * 4);
        }

        // ---- compute current chunk ----
        {
            const uint32_t abuf = Abase + (uint32_t)cur * BUFSZ;
            const uint32_t bbuf = Bbase + (uint32_t)cur * BUFSZ;
#pragma unroll
            for (int ks = 0; ks < 2; ks++) {
                uint32_t Bh[4][4];
#pragma unroll
                for (int jj = 0; jj < 4; jj++)
                    ldsm4(Bh[jj], bbuf + jj * 1280 + ks * 32);
#pragma unroll
                for (int mt = 0; mt < 4; mt++) {
                    uint32_t Ah[4], Al[4];
                    ldsm4(Ah, abuf + mt * 1280 + ks * 32);
                    ldsm4(Al, abuf + OFF_ALO + mt * 1280 + ks * 32);
#pragma unroll
                    for (int jj = 0; jj < 4; jj++) {
#pragma unroll
                        for (int h = 0; h < 2; h++) {
                            float* dd = d[mt][jj * 2 + h];
                            mma_bf16(dd, Ah, Bh[jj][h], Bh[jj][2 + h]);
                            mma_bf16(dd, Al, Bh[jj][h], Bh[jj][2 + h]);
                        }
                    }
                }
            }
        }

        // ---- store key for next chunk, wait Wk copies ----
        if (gc < 127) {
            char* bufp = smem + (size_t)nxt * BUFSZ;
#pragma unroll
            for (int i = 0; i < 4; i++) {
                __nv_bfloat16 h0, h1, h2, h3, l0, l1, l2, l3;
                split2(kreg[i].x, h0, l0); split2(kreg[i].y, h1, l1);
                split2(kreg[i].z, h2, l2); split2(kreg[i].w, h3, l3);
                const int boff = km * 80 + (kc + i * 4) * 2;
                *reinterpret_cast<uint2*>(bufp + boff)           = make_uint2(pkbf(h0, h1), pkbf(h2, h3));
                *reinterpret_cast<uint2*>(bufp + OFF_ALO + boff) = make_uint2(pkbf(l0, l1), pkbf(l2, l3));
            }
            CP_WAIT0();
        }
        __syncthreads();

        // ---- end of pass: tanh + Ws reduction, reset accumulators ----
        if ((gc & 31) == 31) {
            const int o0 = (gc >> 5) * 256;
            const int cb = o0 + wx * 64 + (lane & 3) * 2;
#pragma unroll
            for (int mt = 0; mt < 4; mt++) {
#pragma unroll
                for (int j = 0; j < 8; j++) {
                    const int o = cb + j * 8;
                    const float w0 = wss[o], w1 = wss[o + 1];
                    const float q0 = qbs[o], q1 = qbs[o + 1];
                    part[mt * 2 + 0] += w0 * ftanh(d[mt][j][0] + q0) + w1 * ftanh(d[mt][j][1] + q1);
                    part[mt * 2 + 1] += w0 * ftanh(d[mt][j][2] + q0) + w1 * ftanh(d[mt][j][3] + q1);
                    d[mt][j][0] = 0.0f; d[mt][j][1] = 0.0f;
                    d[mt][j][2] = 0.0f; d[mt][j][3] = 0.0f;
                }
            }
        }
        cur ^= 1;
    }

    // ---- cross-thread reduction ----
#pragma unroll
    for (int i = 0; i < 8; i++) {
        part[i] += __shfl_xor_sync(0xffffffffu, part[i], 1);
        part[i] += __shfl_xor_sync(0xffffffffu, part[i], 2);
    }
    float* red = reinterpret_cast<float*>(smem + SM_RED);
    if ((lane & 3) == 0) {
        const int r0 = wy * 64 + (lane >> 2);
#pragma unroll
        for (int mt = 0; mt < 4; mt++) {
            red[wx * 128 + r0 + mt * 16]     = part[mt * 2 + 0];
            red[wx * 128 + r0 + mt * 16 + 8] = part[mt * 2 + 1];
        }
    }
    __syncthreads();
    if (tid < 128) {
        const float s = red[tid] + red[128 + tid] + red[256 + tid] + red[384 + tid];
        g_score[b * VLEN + v0 + tid] = s;
    }
}

// ---------------------------------------------------------------------------
// Kernel 3: softmax over V=4096 per batch
// ---------------------------------------------------------------------------
__global__ void softmax_kernel(float* __restrict__ attn_out) {
    __shared__ float red[256];
    const int b = blockIdx.x;
    const int t = threadIdx.x;
    const float* s = g_score + b * VLEN;

    float local[16];
    float mx = -1e30f;
#pragma unroll
    for (int i = 0; i < 16; i++) {
        local[i] = s[t + i * 256];
        mx = fmaxf(mx, local[i]);
    }
    red[t] = mx;
    __syncthreads();
    for (int o = 128; o; o >>= 1) {
        if (t < o) red[t] = fmaxf(red[t], red[t + o]);
        __syncthreads();
    }
    mx = red[0];
    __syncthreads();

    float sum = 0.0f;
#pragma unroll
    for (int i = 0; i < 16; i++) {
        local[i] = expf(local[i] - mx);
        sum += local[i];
    }
    red[t] = sum;
    __syncthreads();
    for (int o = 128; o; o >>= 1) {
        if (t < o) red[t] += red[t + o];
        __syncthreads();
    }
    const float inv = 1.0f / red[0];
#pragma unroll
    for (int i = 0; i < 16; i++) attn_out[b * VLEN + t + i * 256] = local[i] * inv;
}

// ---------------------------------------------------------------------------
// Kernel 4a: context partials with v-split (512 blocks for full-chip MLP)
// grid (hc=2, b=32, vs=8), 128 threads; each thread owns 4 h (float4).
// ---------------------------------------------------------------------------
__global__ void context_part_kernel(const float* __restrict__ value,
                                    const float* __restrict__ attn) {
    __shared__ float a_s[512];
    const int hc = blockIdx.x, b = blockIdx.y, vs = blockIdx.z;
    const int v0 = vs * 512;
    const float* ap = attn + b * VLEN + v0;
    for (int i = threadIdx.x; i < 512; i += 128) a_s[i] = ap[i];
    __syncthreads();

    const int h = hc * 512 + threadIdx.x * 4;
    const float* vp = value + ((size_t)b * VLEN + v0) * HDIM + h;
    float ax = 0.f, ay = 0.f, az = 0.f, aw = 0.f;
    for (int v = 0; v < 512; v += 8) {
#pragma unroll
        for (int j = 0; j < 8; j++) {
            const float4 x = *reinterpret_cast<const float4*>(vp + (size_t)(v + j) * HDIM);
            const float a = a_s[v + j];
            ax += a * x.x; ay += a * x.y; az += a * x.z; aw += a * x.w;
        }
    }
    *reinterpret_cast<float4*>(g_ctx_part + ((size_t)vs * BATCH + b) * HDIM + h) =
        make_float4(ax, ay, az, aw);
}

// Kernel 4b: reduce 8 partials
__global__ void context_reduce_kernel(float* __restrict__ ctx) {
    const int i = blockIdx.x * 256 + threadIdx.x;   // 0 .. 32*1024-1
    float s = 0.0f;
#pragma unroll
    for (int vs = 0; vs < 8; vs++) s += g_ctx_part[vs * BATCH * HDIM + i];
    ctx[i] = s;
}

// ---------------------------------------------------------------------------
// Launch. Inputs: query, key, value, Wq, Wk, bias, Ws, bs.
// Output: context (32*1024) then attn (32*4096).
// ---------------------------------------------------------------------------
extern "C" void kernel_launch(void* const* d_in, const int* in_sizes, int n_in,
                              void* d_out, int out_size) {
    const float* query = (const float*)d_in[0];
    const float* key   = (const float*)d_in[1];
    const float* value = (const float*)d_in[2];
    const float* Wq    = (const float*)d_in[3];
    const float* Wk    = (const float*)d_in[4];
    const float* bias  = (const float*)d_in[5];
    const float* Ws    = (const float*)d_in[6];

    float* out  = (float*)d_out;
    float* ctx  = out;                    // (B, 1, H)
    float* attn = out + BATCH * HDIM;     // (B, V)

    cudaFuncSetAttribute(score_kernel, cudaFuncAttributeMaxDynamicSharedMemorySize, SM_TOTAL);

    qb_kernel<<<(BATCH * HDIM * 32) / 256, 256>>>(query, Wq, bias);
    wk_split_kernel<<<(HDIM * HDIM) / (256 * 4), 256>>>(Wk);
    score_kernel<<<dim3(VLEN / 128, BATCH), 256, SM_TOTAL>>>(key, Ws);
    softmax_kernel<<<BATCH, 256>>>(attn);
    context_part_kernel<<<dim3(2, BATCH, 8), 128>>>(value, attn);
    context_reduce_kernel<<<(BATCH * HDIM) / 256, 256>>>(ctx);
}

// round 5
// speedup vs baseline: 3.8266x; 1.5181x over previous
#include <cuda_runtime.h>
#include <cuda_fp16.h>
#include <cstdint>

#define BATCH 32
#define VLEN  4096
#define HDIM  1024

// ---------------- device scratch ----------------
__device__ float g_qb[BATCH * HDIM];
__device__ float g_score[BATCH * VLEN];
__device__ __align__(16) __half g_wk[HDIM * HDIM];
__device__ float g_ctx_part[8 * BATCH * HDIM];   // v-split context partials

// ---------------- helpers ----------------
__device__ __forceinline__ uint32_t smem_u32(const void* p) {
    uint32_t a;
    asm("{ .reg .u64 t; cvta.to.shared.u64 t, %1; cvt.u32.u64 %0, t; }" : "=r"(a) : "l"(p));
    return a;
}
__device__ __forceinline__ void cp16(uint32_t saddr, const void* g) {
    asm volatile("cp.async.cg.shared.global [%0], [%1], 16;" :: "r"(saddr), "l"(g) : "memory");
}
#define CP_COMMIT() asm volatile("cp.async.commit_group;" ::: "memory")
#define CP_WAIT0()  asm volatile("cp.async.wait_group 0;" ::: "memory")

__device__ __forceinline__ void ldsm4(uint32_t* r, uint32_t addr) {
    asm volatile("ldmatrix.sync.aligned.m8n8.x4.shared.b16 {%0,%1,%2,%3}, [%4];"
                 : "=r"(r[0]), "=r"(r[1]), "=r"(r[2]), "=r"(r[3]) : "r"(addr));
}
__device__ __forceinline__ void mma_f16(float* d, const uint32_t* a, uint32_t b0, uint32_t b1) {
    asm volatile("mma.sync.aligned.m16n8k16.row.col.f32.f16.f16.f32 "
                 "{%0,%1,%2,%3}, {%4,%5,%6,%7}, {%8,%9}, {%0,%1,%2,%3};"
                 : "+f"(d[0]), "+f"(d[1]), "+f"(d[2]), "+f"(d[3])
                 : "r"(a[0]), "r"(a[1]), "r"(a[2]), "r"(a[3]), "r"(b0), "r"(b1));
}
__device__ __forceinline__ uint32_t pkh(float a, float b) {
    __half2 h = __floats2half2_rn(a, b);
    return *reinterpret_cast<uint32_t*>(&h);
}
// fast tanh: 1 - 2/(exp(2x)+1); MUFU-based, rel err ~1e-6
__device__ __forceinline__ float ftanh(float x) {
    float e = __expf(2.0f * x);
    return 1.0f - __fdividef(2.0f, e + 1.0f);
}

// ---------------- SMEM layout (bytes) ----------------
// per buffer: [A 10240][B 20480] = 30720; 2 buffers
#define OFF_B    10240
#define BUFSZ    30720
#define SM_QB    (2 * BUFSZ)          // 61440, 1024 floats
#define SM_WS    (SM_QB + 4096)
#define SM_RED   (SM_WS + 4096)
#define SM_TOTAL (SM_RED + 2048)      // 71680

// ---------------------------------------------------------------------------
// Kernel 1: qb[b][o] = bias[o] + sum_h Wq[o][h] * query[b][h]
// ---------------------------------------------------------------------------
__global__ void qb_kernel(const float* __restrict__ query,
                          const float* __restrict__ Wq,
                          const float* __restrict__ bias) {
    int w    = (blockIdx.x * blockDim.x + threadIdx.x) >> 5;
    int lane = threadIdx.x & 31;
    int b = w / HDIM;
    int o = w % HDIM;
    const float* wrow = Wq + (size_t)o * HDIM;
    const float* qrow = query + (size_t)b * HDIM;
    float s = 0.0f;
#pragma unroll 8
    for (int h = lane; h < HDIM; h += 32) s += wrow[h] * qrow[h];
#pragma unroll
    for (int off = 16; off; off >>= 1) s += __shfl_xor_sync(0xffffffffu, s, off);
    if (lane == 0) g_qb[w] = s + bias[o];
}

// ---------------------------------------------------------------------------
// Kernel 1b: convert Wk to fp16
// ---------------------------------------------------------------------------
__global__ void wk_conv_kernel(const float* __restrict__ Wk) {
    int i = (blockIdx.x * 256 + threadIdx.x) * 4;
    float4 w = *reinterpret_cast<const float4*>(Wk + i);
    *reinterpret_cast<uint2*>(g_wk + i) = make_uint2(pkh(w.x, w.y), pkh(w.z, w.w));
}

// ---------------------------------------------------------------------------
// Kernel 2: score GEMM, single fp16 MMA per product (fp32 accumulate).
// Block: 128 v-rows x 256 o-cols per pass, 4 passes. K-chunk 32, double buffer.
// ---------------------------------------------------------------------------
__global__ void __launch_bounds__(256, 1)
score_kernel(const float* __restrict__ key, const float* __restrict__ Ws) {
    extern __shared__ __align__(16) char smem[];
    const uint32_t sb = smem_u32(smem);
    const int tid  = threadIdx.x;
    const int lane = tid & 31;
    const int wid  = tid >> 5;
    const int wy   = wid >> 2;   // 0..1 : M group (64 rows)
    const int wx   = wid & 3;    // 0..3 : N group (64 cols)
    const int b    = blockIdx.y;
    const int v0   = blockIdx.x * 128;

    float* qbs = reinterpret_cast<float*>(smem + SM_QB);
    float* wss = reinterpret_cast<float*>(smem + SM_WS);
#pragma unroll
    for (int i = 0; i < 4; i++) {
        qbs[tid + i * 256] = g_qb[b * HDIM + tid + i * 256];
        wss[tid + i * 256] = Ws[tid + i * 256];
    }

    const float* keyb = key + ((size_t)b * VLEN + v0) * HDIM;

    const int km = tid >> 1;            // key row 0..127
    const int kc = (tid & 1) * 16;      // key col base (fp32)
    const int wn = tid;                 // Wk row 0..255

    const uint32_t aoff  = (uint32_t)((lane & 15) * 80 + (lane >> 4) * 16);
    const uint32_t Abase = sb + (uint32_t)(wy * 64 * 80) + aoff;
    const uint32_t Bbase = sb + OFF_B + (uint32_t)(wx * 64 * 80) + aoff;

    float d[4][8][4];
#pragma unroll
    for (int mt = 0; mt < 4; mt++)
#pragma unroll
        for (int j = 0; j < 8; j++)
#pragma unroll
            for (int q = 0; q < 4; q++) d[mt][j][q] = 0.0f;
    float part[8];
#pragma unroll
    for (int i = 0; i < 8; i++) part[i] = 0.0f;

    float4 kreg[4];

    // ---- prologue: chunk 0 into buffer 0 ----
    {
#pragma unroll
        for (int c = 0; c < 4; c++)
            cp16(sb + OFF_B + wn * 80 + c * 16, g_wk + (size_t)wn * HDIM + c * 8);
        CP_COMMIT();
#pragma unroll
        for (int i = 0; i < 4; i++)
            kreg[i] = *reinterpret_cast<const float4*>(keyb + (size_t)km * HDIM + kc + i * 4);
        char* bufp = smem;
        const int boff = km * 80 + kc * 2;
        *reinterpret_cast<uint4*>(bufp + boff) =
            make_uint4(pkh(kreg[0].x, kreg[0].y), pkh(kreg[0].z, kreg[0].w),
                       pkh(kreg[1].x, kreg[1].y), pkh(kreg[1].z, kreg[1].w));
        *reinterpret_cast<uint4*>(bufp + boff + 16) =
            make_uint4(pkh(kreg[2].x, kreg[2].y), pkh(kreg[2].z, kreg[2].w),
                       pkh(kreg[3].x, kreg[3].y), pkh(kreg[3].z, kreg[3].w));
        CP_WAIT0();
        __syncthreads();
    }

    int cur = 0;
    for (int gc = 0; gc < 128; gc++) {
        const int nxt = cur ^ 1;
        // ---- issue loads for next chunk ----
        if (gc < 127) {
            const int n   = gc + 1;
            const int h0  = (n & 31) * 32;
            const int o0n = (n >> 5) * 256;
            const uint32_t bb = sb + (uint32_t)nxt * BUFSZ;
#pragma unroll
            for (int c = 0; c < 4; c++)
                cp16(bb + OFF_B + wn * 80 + c * 16,
                     g_wk + (size_t)(o0n + wn) * HDIM + h0 + c * 8);
            CP_COMMIT();
#pragma unroll
            for (int i = 0; i < 4; i++)
                kreg[i] = *reinterpret_cast<const float4*>(keyb + (size_t)km * HDIM + h0 + kc + i * 4);
        }

        // ---- compute current chunk ----
        {
            const uint32_t abuf = Abase + (uint32_t)cur * BUFSZ;
            const uint32_t bbuf = Bbase + (uint32_t)cur * BUFSZ;
#pragma unroll
            for (int ks = 0; ks < 2; ks++) {
                uint32_t Bh[4][4];
#pragma unroll
                for (int jj = 0; jj < 4; jj++)
                    ldsm4(Bh[jj], bbuf + jj * 1280 + ks * 32);
#pragma unroll
                for (int mt = 0; mt < 4; mt++) {
                    uint32_t Ah[4];
                    ldsm4(Ah, abuf + mt * 1280 + ks * 32);
#pragma unroll
                    for (int jj = 0; jj < 4; jj++) {
#pragma unroll
                        for (int h = 0; h < 2; h++)
                            mma_f16(d[mt][jj * 2 + h], Ah, Bh[jj][h], Bh[jj][2 + h]);
                    }
                }
            }
        }

        // ---- store key for next chunk, wait Wk copies ----
        if (gc < 127) {
            char* bufp = smem + (size_t)nxt * BUFSZ;
            const int boff = km * 80 + kc * 2;
            *reinterpret_cast<uint4*>(bufp + boff) =
                make_uint4(pkh(kreg[0].x, kreg[0].y), pkh(kreg[0].z, kreg[0].w),
                           pkh(kreg[1].x, kreg[1].y), pkh(kreg[1].z, kreg[1].w));
            *reinterpret_cast<uint4*>(bufp + boff + 16) =
                make_uint4(pkh(kreg[2].x, kreg[2].y), pkh(kreg[2].z, kreg[2].w),
                           pkh(kreg[3].x, kreg[3].y), pkh(kreg[3].z, kreg[3].w));
            CP_WAIT0();
        }
        __syncthreads();

        // ---- end of pass: tanh + Ws reduction, reset accumulators ----
        if ((gc & 31) == 31) {
            const int o0 = (gc >> 5) * 256;
            const int cb = o0 + wx * 64 + (lane & 3) * 2;
#pragma unroll
            for (int mt = 0; mt < 4; mt++) {
#pragma unroll
                for (int j = 0; j < 8; j++) {
                    const int o = cb + j * 8;
                    const float w0 = wss[o], w1 = wss[o + 1];
                    const float q0 = qbs[o], q1 = qbs[o + 1];
                    part[mt * 2 + 0] += w0 * ftanh(d[mt][j][0] + q0) + w1 * ftanh(d[mt][j][1] + q1);
                    part[mt * 2 + 1] += w0 * ftanh(d[mt][j][2] + q0) + w1 * ftanh(d[mt][j][3] + q1);
                    d[mt][j][0] = 0.0f; d[mt][j][1] = 0.0f;
                    d[mt][j][2] = 0.0f; d[mt][j][3] = 0.0f;
                }
            }
        }
        cur ^= 1;
    }

    // ---- cross-thread reduction ----
#pragma unroll
    for (int i = 0; i < 8; i++) {
        part[i] += __shfl_xor_sync(0xffffffffu, part[i], 1);
        part[i] += __shfl_xor_sync(0xffffffffu, part[i], 2);
    }
    float* red = reinterpret_cast<float*>(smem + SM_RED);
    if ((lane & 3) == 0) {
        const int r0 = wy * 64 + (lane >> 2);
#pragma unroll
        for (int mt = 0; mt < 4; mt++) {
            red[wx * 128 + r0 + mt * 16]     = part[mt * 2 + 0];
            red[wx * 128 + r0 + mt * 16 + 8] = part[mt * 2 + 1];
        }
    }
    __syncthreads();
    if (tid < 128) {
        const float s = red[tid] + red[128 + tid] + red[256 + tid] + red[384 + tid];
        g_score[b * VLEN + v0 + tid] = s;
    }
}

// ---------------------------------------------------------------------------
// Kernel 3: softmax over V=4096 per batch
// ---------------------------------------------------------------------------
__global__ void softmax_kernel(float* __restrict__ attn_out) {
    __shared__ float red[256];
    const int b = blockIdx.x;
    const int t = threadIdx.x;
    const float* s = g_score + b * VLEN;

    float local[16];
    float mx = -1e30f;
#pragma unroll
    for (int i = 0; i < 16; i++) {
        local[i] = s[t + i * 256];
        mx = fmaxf(mx, local[i]);
    }
    red[t] = mx;
    __syncthreads();
    for (int o = 128; o; o >>= 1) {
        if (t < o) red[t] = fmaxf(red[t], red[t + o]);
        __syncthreads();
    }
    mx = red[0];
    __syncthreads();

    float sum = 0.0f;
#pragma unroll
    for (int i = 0; i < 16; i++) {
        local[i] = expf(local[i] - mx);
        sum += local[i];
    }
    red[t] = sum;
    __syncthreads();
    for (int o = 128; o; o >>= 1) {
        if (t < o) red[t] += red[t + o];
        __syncthreads();
    }
    const float inv = 1.0f / red[0];
#pragma unroll
    for (int i = 0; i < 16; i++) attn_out[b * VLEN + t + i * 256] = local[i] * inv;
}

// ---------------------------------------------------------------------------
// Kernel 4a: context partials with v-split (512 blocks for full-chip MLP)
// ---------------------------------------------------------------------------
__global__ void context_part_kernel(const float* __restrict__ value,
                                    const float* __restrict__ attn) {
    __shared__ float a_s[512];
    const int hc = blockIdx.x, b = blockIdx.y, vs = blockIdx.z;
    const int v0 = vs * 512;
    const float* ap = attn + b * VLEN + v0;
    for (int i = threadIdx.x; i < 512; i += 128) a_s[i] = ap[i];
    __syncthreads();

    const int h = hc * 512 + threadIdx.x * 4;
    const float* vp = value + ((size_t)b * VLEN + v0) * HDIM + h;
    float ax = 0.f, ay = 0.f, az = 0.f, aw = 0.f;
    for (int v = 0; v < 512; v += 8) {
#pragma unroll
        for (int j = 0; j < 8; j++) {
            const float4 x = *reinterpret_cast<const float4*>(vp + (size_t)(v + j) * HDIM);
            const float a = a_s[v + j];
            ax += a * x.x; ay += a * x.y; az += a * x.z; aw += a * x.w;
        }
    }
    *reinterpret_cast<float4*>(g_ctx_part + ((size_t)vs * BATCH + b) * HDIM + h) =
        make_float4(ax, ay, az, aw);
}

// Kernel 4b: reduce 8 partials
__global__ void context_reduce_kernel(float* __restrict__ ctx) {
    const int i = blockIdx.x * 256 + threadIdx.x;
    float s = 0.0f;
#pragma unroll
    for (int vs = 0; vs < 8; vs++) s += g_ctx_part[vs * BATCH * HDIM + i];
    ctx[i] = s;
}

// ---------------------------------------------------------------------------
// Launch. Inputs: query, key, value, Wq, Wk, bias, Ws, bs.
// Output: context (32*1024) then attn (32*4096).
// ---------------------------------------------------------------------------
extern "C" void kernel_launch(void* const* d_in, const int* in_sizes, int n_in,
                              void* d_out, int out_size) {
    const float* query = (const float*)d_in[0];
    const float* key   = (const float*)d_in[1];
    const float* value = (const float*)d_in[2];
    const float* Wq    = (const float*)d_in[3];
    const float* Wk    = (const float*)d_in[4];
    const float* bias  = (const float*)d_in[5];
    const float* Ws    = (const float*)d_in[6];

    float* out  = (float*)d_out;
    float* ctx  = out;                    // (B, 1, H)
    float* attn = out + BATCH * HDIM;     // (B, V)

    cudaFuncSetAttribute(score_kernel, cudaFuncAttributeMaxDynamicSharedMemorySize, SM_TOTAL);

    qb_kernel<<<(BATCH * HDIM * 32) / 256, 256>>>(query, Wq, bias);
    wk_conv_kernel<<<(HDIM * HDIM) / (256 * 4), 256>>>(Wk);
    score_kernel<<<dim3(VLEN / 128, BATCH), 256, SM_TOTAL>>>(key, Ws);
    softmax_kernel<<<BATCH, 256>>>(attn);
    context_part_kernel<<<dim3(2, BATCH, 8), 128>>>(value, attn);
    context_reduce_kernel<<<(BATCH * HDIM) / 256, 256>>>(ctx);
}